// round 7
// baseline (speedup 1.0000x reference)
#include <cuda_runtime.h>
#include <cstdint>

#define BB 4
#define NN 8192
#define KK 16
#define O1 64
#define HH 128
#define TOT (BB*NN)
#define BN_EPS 1e-5f
#define NORM_EPSF 1e-12f
#define SLOPE 0.2f

// knn config
#define SPL 4                 // candidate splits per query
#define SPLEN (NN/SPL)        // 2048 candidates per split
#define TE 256                // candidates per split per tile iteration
#define NIT (SPLEN/TE)        // 8 tile iterations
#define NACC 8                // chunk-min accumulators per lane (chunks of 256)
#define CAP 32                // survivor capacity per (query,split), power of two
#define PADF (TE+4)           // padded float stride (bank-shift between splits)

typedef unsigned long long u64;
__device__ __forceinline__ u64 FMA2(u64 a, u64 b, u64 c) {
    u64 d; asm("fma.rn.f32x2 %0, %1, %2, %3;" : "=l"(d) : "l"(a), "l"(b), "l"(c)); return d;
}
__device__ __forceinline__ u64 MUL2(u64 a, u64 b) {
    u64 d; asm("mul.rn.f32x2 %0, %1, %2;" : "=l"(d) : "l"(a), "l"(b)); return d;
}
__device__ __forceinline__ float LO2(u64 v) { return __uint_as_float((unsigned)v); }
__device__ __forceinline__ float HI2(u64 v) { return __uint_as_float((unsigned)(v >> 32)); }
__device__ __forceinline__ u64 BC2(float v) { unsigned u = __float_as_uint(v); return (u64)u | ((u64)u << 32); }

// ---------------- scratch (static device globals; no allocation) ----------------
__device__ float  d_cent[BB][3];
__device__ float  d_g[BB][NN];
__device__ float  d_gcn[BB][NN][3];
__device__ float4 d_pts4[BB][NN];          // packed (x,y,z,|p|^2)
__device__ double d_sstat[4];
__device__ float  d_amin[BB][NN];
__device__ float  d_amax[BB][NN];
__device__ float  d_pre[2][BB][HH][NN];
__device__ double d_cstat[4][HH];

// ---------------- K0 ----------------
__global__ void k_zero() {
    if (threadIdx.x < 4) d_sstat[threadIdx.x] = 0.0;
}

// ---------------- K1: centroid ----------------
__global__ void k_centroid(const float* __restrict__ pts) {
    int b = blockIdx.x / 3, c = blockIdx.x % 3;
    const float* p = pts + (b * 3 + c) * NN;
    float s = 0.f;
    for (int n = threadIdx.x; n < NN; n += 256) s += p[n];
    __shared__ float sm[256];
    sm[threadIdx.x] = s; __syncthreads();
    for (int o = 128; o; o >>= 1) {
        if (threadIdx.x < o) sm[threadIdx.x] += sm[threadIdx.x + o];
        __syncthreads();
    }
    if (threadIdx.x == 0) d_cent[b][c] = sm[0] * (1.f / NN);
}

// ---------------- K2: g, normalized p2gc, g stats, packed pts4 ----------------
__global__ void k_prep(const float* __restrict__ pts) {
    int i = blockIdx.x * 256 + threadIdx.x;
    int b = i >> 13, n = i & (NN - 1);
    float x = pts[(b * 3 + 0) * NN + n];
    float y = pts[(b * 3 + 1) * NN + n];
    float z = pts[(b * 3 + 2) * NN + n];
    d_pts4[b][n] = make_float4(x, y, z, fmaf(x, x, fmaf(y, y, z * z)));

    float vx = x - d_cent[b][0];
    float vy = y - d_cent[b][1];
    float vz = z - d_cent[b][2];
    float g = vx * vx + vy * vy + vz * vz;
    d_g[b][n] = g;
    float inv = 1.f / fmaxf(sqrtf(g), NORM_EPSF);
    d_gcn[b][n][0] = vx * inv;
    d_gcn[b][n][1] = vy * inv;
    d_gcn[b][n][2] = vz * inv;

    __shared__ float s1[256], s2[256];
    s1[threadIdx.x] = g; s2[threadIdx.x] = g * g;
    __syncthreads();
    for (int o = 128; o; o >>= 1) {
        if (threadIdx.x < o) { s1[threadIdx.x] += s1[threadIdx.x + o]; s2[threadIdx.x] += s2[threadIdx.x + o]; }
        __syncthreads();
    }
    if (threadIdx.x == 0) {
        atomicAdd(&d_sstat[0], (double)s1[0]);
        atomicAdd(&d_sstat[1], (double)s2[0]);
    }
}

// ---------------- K3: kNN, split-parallel threshold filter (shared tight tau) ----------------
// Block = 256 threads = 8 warps. Warp = 8 queries x 4 splits (lane = split*8 + q).
// tau = max over splits of (4th smallest of 8 chunk-minima) -> >=16 keys <= tau globally.
__global__ void __launch_bounds__(256, 4) k_knn() {
    __shared__ __align__(16) float sx[SPL * PADF], sy[SPL * PADF], sz[SPL * PADF], sw[SPL * PADF];
    __shared__ unsigned short sbuf[CAP][256];
    int tid = threadIdx.x;
    int w = tid >> 5, lane = tid & 31;
    int sp = lane >> 3, qq = lane & 7;
    int b = blockIdx.x >> 7;                              // 128 blocks/batch
    int qn = ((blockIdx.x & 127) << 6) | (w << 3) | qq;   // 64 queries/block
    const float4* __restrict__ P = &d_pts4[b][0];
    float4 q = P[qn];
    u64 qx2 = BC2(q.x), qy2 = BC2(q.y), qz2 = BC2(q.z), n22 = BC2(-2.f);
    const float* bx = &sx[sp * PADF];
    const float* by = &sy[sp * PADF];
    const float* bz = &sz[sp * PADF];
    const float* bw = &sw[sp * PADF];

    // ---- pass 1: 8 chunk minima (chunks of 256) over this lane's split ----
    float m[NACC];
#pragma unroll
    for (int i = 0; i < NACC; i++) m[i] = 3.4e38f;

    for (int it = 0; it < NIT; it++) {
        __syncthreads();
#pragma unroll
        for (int r = 0; r < 4; r++) {
            int p = r * 256 + tid;                         // 0..1023 = 4 splits x 256
            int ls = p >> 8, e = p & (TE - 1);
            float4 c = P[ls * SPLEN + it * TE + e];
            sx[ls * PADF + e] = c.x; sy[ls * PADF + e] = c.y;
            sz[ls * PADF + e] = c.z; sw[ls * PADF + e] = c.w;
        }
        __syncthreads();
#pragma unroll 16
        for (int e = 0; e < TE; e += 4) {
            ulonglong2 X = *(const ulonglong2*)(bx + e);
            ulonglong2 Y = *(const ulonglong2*)(by + e);
            ulonglong2 Z = *(const ulonglong2*)(bz + e);
            ulonglong2 W = *(const ulonglong2*)(bw + e);
            u64 k0 = FMA2(n22, FMA2(qx2, X.x, FMA2(qy2, Y.x, MUL2(qz2, Z.x))), W.x);
            u64 k1 = FMA2(n22, FMA2(qx2, X.y, FMA2(qy2, Y.y, MUL2(qz2, Z.y))), W.y);
            m[(e + 0) & (NACC - 1)] = fminf(m[(e + 0) & (NACC - 1)], LO2(k0));
            m[(e + 1) & (NACC - 1)] = fminf(m[(e + 1) & (NACC - 1)], HI2(k0));
            m[(e + 2) & (NACC - 1)] = fminf(m[(e + 2) & (NACC - 1)], LO2(k1));
            m[(e + 3) & (NACC - 1)] = fminf(m[(e + 3) & (NACC - 1)], HI2(k1));
        }
    }

    // sort the 8 chunk minima ascending (bitonic), take 4th smallest
#pragma unroll
    for (int kk = 2; kk <= NACC; kk <<= 1) {
#pragma unroll
        for (int j = kk >> 1; j > 0; j >>= 1) {
#pragma unroll
            for (int i = 0; i < NACC; i++) {
                int ixj = i ^ j;
                if (ixj > i) {
                    bool up = ((i & kk) == 0);
                    float lo = fminf(m[i], m[ixj]);
                    float hi = fmaxf(m[i], m[ixj]);
                    m[i] = up ? lo : hi;
                    m[ixj] = up ? hi : lo;
                }
            }
        }
    }
    // shared tau across the query's 4 split lanes: max of per-split 4th-smallest.
    float tau = m[3];
    tau = fmaxf(tau, __shfl_xor_sync(0xffffffffu, tau, 8));
    tau = fmaxf(tau, __shfl_xor_sync(0xffffffffu, tau, 16));

    // ---- pass 2: collect survivor local indices (u16), branchless ----
    int cnt = 0;
    for (int it = 0; it < NIT; it++) {
        __syncthreads();
#pragma unroll
        for (int r = 0; r < 4; r++) {
            int p = r * 256 + tid;
            int ls = p >> 8, e = p & (TE - 1);
            float4 c = P[ls * SPLEN + it * TE + e];
            sx[ls * PADF + e] = c.x; sy[ls * PADF + e] = c.y;
            sz[ls * PADF + e] = c.z; sw[ls * PADF + e] = c.w;
        }
        __syncthreads();
        int jb = it * TE;
#pragma unroll 8
        for (int e = 0; e < TE; e += 4) {
            ulonglong2 X = *(const ulonglong2*)(bx + e);
            ulonglong2 Y = *(const ulonglong2*)(by + e);
            ulonglong2 Z = *(const ulonglong2*)(bz + e);
            ulonglong2 W = *(const ulonglong2*)(bw + e);
            u64 k0 = FMA2(n22, FMA2(qx2, X.x, FMA2(qy2, Y.x, MUL2(qz2, Z.x))), W.x);
            u64 k1 = FMA2(n22, FMA2(qx2, X.y, FMA2(qy2, Y.y, MUL2(qz2, Z.y))), W.y);
            sbuf[cnt & (CAP - 1)][tid] = (unsigned short)(jb + e + 0);
            cnt += (LO2(k0) <= tau) ? 1 : 0;
            sbuf[cnt & (CAP - 1)][tid] = (unsigned short)(jb + e + 1);
            cnt += (HI2(k0) <= tau) ? 1 : 0;
            sbuf[cnt & (CAP - 1)][tid] = (unsigned short)(jb + e + 2);
            cnt += (LO2(k1) <= tau) ? 1 : 0;
            sbuf[cnt & (CAP - 1)][tid] = (unsigned short)(jb + e + 3);
            cnt += (HI2(k1) <= tau) ? 1 : 0;
        }
    }
    __syncwarp();

    // broadcast per-split survivor counts to the merger lanes
    int c0 = __shfl_sync(0xffffffffu, cnt, qq);
    int c1 = __shfl_sync(0xffffffffu, cnt, 8 + qq);
    int c2 = __shfl_sync(0xffffffffu, cnt, 16 + qq);
    int c3 = __shfl_sync(0xffffffffu, cnt, 24 + qq);

    float asum = 0.f, asq = 0.f;
    if (sp == 0) {
        // exact top-16 merge, ascending split order then ascending index => reference ties
        float nd[KK]; int ni[KK];
#pragma unroll
        for (int s = 0; s < KK; s++) { nd[s] = 3.4e38f; ni[s] = 0; }
        float worst = 3.4e38f; int wslot = 0;
#pragma unroll
        for (int ss = 0; ss < SPL; ss++) {
            int c = ss == 0 ? c0 : (ss == 1 ? c1 : (ss == 2 ? c2 : c3));
            int col = (w << 5) + ss * 8 + qq;
            if (c < CAP) {
                for (int ii = 0; ii < c; ii++) {
                    int j = ss * SPLEN + sbuf[ii][col];
                    float4 cc = __ldg(&P[j]);
                    float key = fmaf(-2.f, fmaf(q.x, cc.x, fmaf(q.y, cc.y, q.z * cc.z)), cc.w);
                    if (key < worst) {
#pragma unroll
                        for (int s = 0; s < KK; s++) if (s == wslot) { nd[s] = key; ni[s] = j; }
                        worst = nd[0]; wslot = 0;
#pragma unroll
                        for (int s = 1; s < KK; s++) if (nd[s] > worst) { worst = nd[s]; wslot = s; }
                    }
                }
            } else {
                // overflow fallback (rare): exact rescan of this split
                for (int j = ss * SPLEN; j < ss * SPLEN + SPLEN; j++) {
                    float4 cc = __ldg(&P[j]);
                    float key = fmaf(-2.f, fmaf(q.x, cc.x, fmaf(q.y, cc.y, q.z * cc.z)), cc.w);
                    if (key < worst) {
#pragma unroll
                        for (int s = 0; s < KK; s++) if (s == wslot) { nd[s] = key; ni[s] = j; }
                        worst = nd[0]; wslot = 0;
#pragma unroll
                        for (int s = 1; s < KK; s++) if (nd[s] > worst) { worst = nd[s]; wslot = s; }
                    }
                }
            }
        }

        // alpha epilogue over the 16 kept neighbors
        float gx = d_gcn[b][qn][0], gy = d_gcn[b][qn][1], gz = d_gcn[b][qn][2];
        float amin = 3.4e38f, amax = -3.4e38f;
#pragma unroll
        for (int s = 0; s < KK; s++) {
            int j = ni[s];
            float4 cc = __ldg(&P[j]);
            float vx = cc.x - q.x, vy = cc.y - q.y, vz = cc.z - q.z;
            float inv = 1.f / fmaxf(sqrtf(fmaf(vx, vx, fmaf(vy, vy, vz * vz))), NORM_EPSF);
            float al = fmaf(vx, gx, fmaf(vy, gy, vz * gz)) * inv;
            amin = fminf(amin, al); amax = fmaxf(amax, al);
            asum += al; asq = fmaf(al, al, asq);
        }
        d_amin[b][qn] = amin; d_amax[b][qn] = amax;
    }

    // warp reduction of alpha stats (non-merger lanes contribute 0)
#pragma unroll
    for (int o = 16; o; o >>= 1) {
        asum += __shfl_xor_sync(0xffffffffu, asum, o);
        asq  += __shfl_xor_sync(0xffffffffu, asq, o);
    }
    if (lane == 0) {
        atomicAdd(&d_sstat[2], (double)asum);
        atomicAdd(&d_sstat[3], (double)asq);
    }
}

// ---------------- K4: per-point 64-ch activation + 64->128 matvec ----------------
__global__ void __launch_bounds__(256) k_mlp(
    const float* __restrict__ W1d, const float* __restrict__ G1d, const float* __restrict__ B1d,
    const float* __restrict__ W2d,
    const float* __restrict__ W1a, const float* __restrict__ G1a, const float* __restrict__ B1a,
    const float* __restrict__ W2a) {
    __shared__ float sS[O1], sT[O1];
    __shared__ __align__(16) float sW[HH * O1];
    int tid = threadIdx.x;
    int i = blockIdx.x * 256 + tid;
    int b = i >> 13, n = i & (NN - 1);
    float gval = d_g[b][n];
    float amin = d_amin[b][n], amax = d_amax[b][n];

#pragma unroll
    for (int br = 0; br < 2; br++) {
        __syncthreads();
        double cnt = br ? (double)TOT * KK : (double)TOT;
        double mu = d_sstat[2 * br] / cnt;
        float vg = (float)(d_sstat[2 * br + 1] / cnt - mu * mu);
        float mg = (float)mu;
        const float* W1 = br ? W1a : W1d;
        const float* G1 = br ? G1a : G1d;
        const float* B1 = br ? B1a : B1d;
        const float* W2 = br ? W2a : W2d;
        if (tid < O1) {
            float w = W1[tid];
            float sc = w * G1[tid] * rsqrtf(fmaf(w * w, vg, BN_EPS));
            sS[tid] = sc;
            sT[tid] = fmaf(-mg, sc, B1[tid]);
        }
        for (int x = tid; x < HH * O1 / 4; x += 256)
            reinterpret_cast<float4*>(sW)[x] = reinterpret_cast<const float4*>(W2)[x];
        __syncthreads();

        float act[O1];
#pragma unroll
        for (int o = 0; o < O1; o++) {
            float s = sS[o];
            float x = br ? (s >= 0.f ? amax : amin) : gval;
            float y = fmaf(x, s, sT[o]);
            act[o] = y >= 0.f ? y : SLOPE * y;
        }

        float* pre = &d_pre[br][b][0][n];
        for (int h0 = 0; h0 < HH; h0 += 4) {
            float a0 = 0.f, a1 = 0.f, a2 = 0.f, a3 = 0.f;
#pragma unroll
            for (int o = 0; o < O1; o += 4) {
                float4 w0 = *reinterpret_cast<const float4*>(&sW[(h0 + 0) * O1 + o]);
                float4 w1 = *reinterpret_cast<const float4*>(&sW[(h0 + 1) * O1 + o]);
                float4 w2 = *reinterpret_cast<const float4*>(&sW[(h0 + 2) * O1 + o]);
                float4 w3 = *reinterpret_cast<const float4*>(&sW[(h0 + 3) * O1 + o]);
                a0 = fmaf(w0.x, act[o], fmaf(w0.y, act[o + 1], fmaf(w0.z, act[o + 2], fmaf(w0.w, act[o + 3], a0))));
                a1 = fmaf(w1.x, act[o], fmaf(w1.y, act[o + 1], fmaf(w1.z, act[o + 2], fmaf(w1.w, act[o + 3], a1))));
                a2 = fmaf(w2.x, act[o], fmaf(w2.y, act[o + 1], fmaf(w2.z, act[o + 2], fmaf(w2.w, act[o + 3], a2))));
                a3 = fmaf(w3.x, act[o], fmaf(w3.y, act[o + 1], fmaf(w3.z, act[o + 2], fmaf(w3.w, act[o + 3], a3))));
            }
            pre[(h0 + 0) * NN] = a0;
            pre[(h0 + 1) * NN] = a1;
            pre[(h0 + 2) * NN] = a2;
            pre[(h0 + 3) * NN] = a3;
        }
    }
}

// ---------------- K4b: per-channel BN stats for layer 2 ----------------
__global__ void k_cstat() {
    int br = blockIdx.x >> 7;
    int h = blockIdx.x & 127;
    float s = 0.f, q = 0.f;
    for (int bb = 0; bb < BB; bb++) {
        const float* row = &d_pre[br][bb][h][0];
        for (int n = threadIdx.x; n < NN; n += 256) {
            float v = row[n];
            s += v; q = fmaf(v, v, q);
        }
    }
    __shared__ float s1[256], s2[256];
    s1[threadIdx.x] = s; s2[threadIdx.x] = q;
    __syncthreads();
    for (int o = 128; o; o >>= 1) {
        if (threadIdx.x < o) { s1[threadIdx.x] += s1[threadIdx.x + o]; s2[threadIdx.x] += s2[threadIdx.x + o]; }
        __syncthreads();
    }
    if (threadIdx.x == 0) {
        d_cstat[2 * br][h] = (double)s1[0];
        d_cstat[2 * br + 1][h] = (double)s2[0];
    }
}

// ---------------- K5: final BN + LeakyReLU + concat write ----------------
__global__ void k_out(const float* __restrict__ G2d, const float* __restrict__ B2d,
                      const float* __restrict__ G2a, const float* __restrict__ B2a,
                      float* __restrict__ out) {
    __shared__ float sc[2 * HH], sh[2 * HH];
    int tid = threadIdx.x;
    if (tid < 2 * HH) {
        int br = tid >> 7, h = tid & 127;
        double mu = d_cstat[2 * br][h] / TOT;
        float var = (float)(d_cstat[2 * br + 1][h] / TOT - mu * mu);
        float gam = br ? G2a[h] : G2d[h];
        float bet = br ? B2a[h] : B2d[h];
        float s = gam * rsqrtf(var + BN_EPS);
        sc[tid] = s;
        sh[tid] = fmaf(-(float)mu, s, bet);
    }
    __syncthreads();
    const int total = BB * 2 * HH * NN;
    for (int idx = blockIdx.x * 256 + tid; idx < total; idx += gridDim.x * 256) {
        int b = idx >> 21;
        int c = (idx >> 13) & 255;
        int n = idx & (NN - 1);
        float v = d_pre[c >> 7][b][c & 127][n];
        float y = fmaf(v, sc[c], sh[c]);
        out[idx] = y >= 0.f ? y : SLOPE * y;
    }
}

// ---------------- launcher ----------------
extern "C" void kernel_launch(void* const* d_in, const int* in_sizes, int n_in,
                              void* d_out, int out_size) {
    const float* pts = (const float*)d_in[0];
    int base = 2;
    if (n_in >= 2 && in_sizes[1] > 1) base = 1;
    const float* W1d = (const float*)d_in[base + 0];
    const float* G1d = (const float*)d_in[base + 1];
    const float* B1d = (const float*)d_in[base + 2];
    const float* W2d = (const float*)d_in[base + 3];
    const float* G2d = (const float*)d_in[base + 4];
    const float* B2d = (const float*)d_in[base + 5];
    const float* W1a = (const float*)d_in[base + 6];
    const float* G1a = (const float*)d_in[base + 7];
    const float* B1a = (const float*)d_in[base + 8];
    const float* W2a = (const float*)d_in[base + 9];
    const float* G2a = (const float*)d_in[base + 10];
    const float* B2a = (const float*)d_in[base + 11];
    float* out = (float*)d_out;

    k_zero<<<1, 32>>>();
    k_centroid<<<12, 256>>>(pts);
    k_prep<<<TOT / 256, 256>>>(pts);
    k_knn<<<512, 256>>>();
    k_mlp<<<TOT / 256, 256>>>(W1d, G1d, B1d, W2d, W1a, G1a, B1a, W2a);
    k_cstat<<<2 * HH, 256>>>();
    k_out<<<512, 256>>>(G2d, B2d, G2a, B2a, out);
}

// round 8
// speedup vs baseline: 1.7545x; 1.7545x over previous
#include <cuda_runtime.h>
#include <cstdint>

#define BB 4
#define NN 8192
#define KK 16
#define O1 64
#define HH 128
#define TOT (BB*NN)
#define BN_EPS 1e-5f
#define NORM_EPSF 1e-12f
#define SLOPE 0.2f

// knn config: one lane per query (R5 structure), packed f32x2 math
#define TPB 128               // threads (=queries) per block
#define TILE 512              // candidates per smem tile
#define NIT (NN/TILE)         // 16 tile iterations
#define CAP 64                // survivor capacity per query (power of two)

typedef unsigned long long u64;
__device__ __forceinline__ u64 FMA2(u64 a, u64 b, u64 c) {
    u64 d; asm("fma.rn.f32x2 %0, %1, %2, %3;" : "=l"(d) : "l"(a), "l"(b), "l"(c)); return d;
}
__device__ __forceinline__ u64 MUL2(u64 a, u64 b) {
    u64 d; asm("mul.rn.f32x2 %0, %1, %2;" : "=l"(d) : "l"(a), "l"(b)); return d;
}
__device__ __forceinline__ float LO2(u64 v) { return __uint_as_float((unsigned)v); }
__device__ __forceinline__ float HI2(u64 v) { return __uint_as_float((unsigned)(v >> 32)); }
__device__ __forceinline__ u64 BC2(float v) { unsigned u = __float_as_uint(v); return (u64)u | ((u64)u << 32); }

// ---------------- scratch (static device globals; no allocation) ----------------
__device__ float  d_cent[BB][3];
__device__ float  d_g[BB][NN];
__device__ float  d_gcn[BB][NN][3];
__device__ float4 d_pts4[BB][NN];          // packed (x,y,z,|p|^2)
__device__ double d_sstat[4];
__device__ float  d_amin[BB][NN];
__device__ float  d_amax[BB][NN];
__device__ float  d_pre[2][BB][HH][NN];
__device__ double d_cstat[4][HH];

// ---------------- K0 ----------------
__global__ void k_zero() {
    if (threadIdx.x < 4) d_sstat[threadIdx.x] = 0.0;
}

// ---------------- K1: centroid ----------------
__global__ void k_centroid(const float* __restrict__ pts) {
    int b = blockIdx.x / 3, c = blockIdx.x % 3;
    const float* p = pts + (b * 3 + c) * NN;
    float s = 0.f;
    for (int n = threadIdx.x; n < NN; n += 256) s += p[n];
    __shared__ float sm[256];
    sm[threadIdx.x] = s; __syncthreads();
    for (int o = 128; o; o >>= 1) {
        if (threadIdx.x < o) sm[threadIdx.x] += sm[threadIdx.x + o];
        __syncthreads();
    }
    if (threadIdx.x == 0) d_cent[b][c] = sm[0] * (1.f / NN);
}

// ---------------- K2: g, normalized p2gc, g stats, packed pts4 ----------------
__global__ void k_prep(const float* __restrict__ pts) {
    int i = blockIdx.x * 256 + threadIdx.x;
    int b = i >> 13, n = i & (NN - 1);
    float x = pts[(b * 3 + 0) * NN + n];
    float y = pts[(b * 3 + 1) * NN + n];
    float z = pts[(b * 3 + 2) * NN + n];
    d_pts4[b][n] = make_float4(x, y, z, fmaf(x, x, fmaf(y, y, z * z)));

    float vx = x - d_cent[b][0];
    float vy = y - d_cent[b][1];
    float vz = z - d_cent[b][2];
    float g = vx * vx + vy * vy + vz * vz;
    d_g[b][n] = g;
    float inv = 1.f / fmaxf(sqrtf(g), NORM_EPSF);
    d_gcn[b][n][0] = vx * inv;
    d_gcn[b][n][1] = vy * inv;
    d_gcn[b][n][2] = vz * inv;

    __shared__ float s1[256], s2[256];
    s1[threadIdx.x] = g; s2[threadIdx.x] = g * g;
    __syncthreads();
    for (int o = 128; o; o >>= 1) {
        if (threadIdx.x < o) { s1[threadIdx.x] += s1[threadIdx.x + o]; s2[threadIdx.x] += s2[threadIdx.x + o]; }
        __syncthreads();
    }
    if (threadIdx.x == 0) {
        atomicAdd(&d_sstat[0], (double)s1[0]);
        atomicAdd(&d_sstat[1], (double)s2[0]);
    }
}

// ---------------- K3: kNN, R5 structure + packed f32x2 + SoA tiles ----------------
// One lane per query. tau = 16th smallest of 32 interleaved chunk minima (chunks of 256).
__global__ void __launch_bounds__(TPB, 4) k_knn() {
    __shared__ __align__(16) float sx[TILE], sy[TILE], sz[TILE], sw[TILE];
    __shared__ unsigned short sbuf[CAP][TPB];              // [slot][lane]: conflict-free
    int tid = threadIdx.x;
    int b = blockIdx.x >> 6;                               // 64 blocks per batch
    int qn = ((blockIdx.x & 63) << 7) | tid;               // 128 queries per block
    const float4* __restrict__ P = &d_pts4[b][0];
    float4 q = P[qn];
    u64 qx2 = BC2(q.x), qy2 = BC2(q.y), qz2 = BC2(q.z), n22 = BC2(-2.f);

    // ---- pass 1: 32 interleaved chunk minima (each sees 256 candidates) ----
    float m[32];
#pragma unroll
    for (int i = 0; i < 32; i++) m[i] = 3.4e38f;

    for (int it = 0; it < NIT; it++) {
        __syncthreads();
#pragma unroll
        for (int r = 0; r < TILE / TPB; r++) {
            int e = r * TPB + tid;
            float4 c = P[it * TILE + e];
            sx[e] = c.x; sy[e] = c.y; sz[e] = c.z; sw[e] = c.w;
        }
        __syncthreads();
#pragma unroll 16
        for (int e = 0; e < TILE; e += 4) {
            ulonglong2 X = *(const ulonglong2*)(sx + e);
            ulonglong2 Y = *(const ulonglong2*)(sy + e);
            ulonglong2 Z = *(const ulonglong2*)(sz + e);
            ulonglong2 W = *(const ulonglong2*)(sw + e);
            u64 k0 = FMA2(n22, FMA2(qx2, X.x, FMA2(qy2, Y.x, MUL2(qz2, Z.x))), W.x);
            u64 k1 = FMA2(n22, FMA2(qx2, X.y, FMA2(qy2, Y.y, MUL2(qz2, Z.y))), W.y);
            m[(e + 0) & 31] = fminf(m[(e + 0) & 31], LO2(k0));
            m[(e + 1) & 31] = fminf(m[(e + 1) & 31], HI2(k0));
            m[(e + 2) & 31] = fminf(m[(e + 2) & 31], LO2(k1));
            m[(e + 3) & 31] = fminf(m[(e + 3) & 31], HI2(k1));
        }
    }

    // tau = 16th smallest of the 32 chunk minima (>= true 16th-smallest key).
#pragma unroll
    for (int kk = 2; kk <= 32; kk <<= 1) {
#pragma unroll
        for (int j = kk >> 1; j > 0; j >>= 1) {
#pragma unroll
            for (int i = 0; i < 32; i++) {
                int ixj = i ^ j;
                if (ixj > i) {
                    bool up = ((i & kk) == 0);
                    float lo = fminf(m[i], m[ixj]);
                    float hi = fmaxf(m[i], m[ixj]);
                    m[i] = up ? lo : hi;
                    m[ixj] = up ? hi : lo;
                }
            }
        }
    }
    float tau = m[15];

    // ---- pass 2: collect survivor indices (u16), branchless unconditional store ----
    int cnt = 0;
    for (int it = 0; it < NIT; it++) {
        __syncthreads();
#pragma unroll
        for (int r = 0; r < TILE / TPB; r++) {
            int e = r * TPB + tid;
            float4 c = P[it * TILE + e];
            sx[e] = c.x; sy[e] = c.y; sz[e] = c.z; sw[e] = c.w;
        }
        __syncthreads();
        int jb = it * TILE;
#pragma unroll 8
        for (int e = 0; e < TILE; e += 4) {
            ulonglong2 X = *(const ulonglong2*)(sx + e);
            ulonglong2 Y = *(const ulonglong2*)(sy + e);
            ulonglong2 Z = *(const ulonglong2*)(sz + e);
            ulonglong2 W = *(const ulonglong2*)(sw + e);
            u64 k0 = FMA2(n22, FMA2(qx2, X.x, FMA2(qy2, Y.x, MUL2(qz2, Z.x))), W.x);
            u64 k1 = FMA2(n22, FMA2(qx2, X.y, FMA2(qy2, Y.y, MUL2(qz2, Z.y))), W.y);
            sbuf[cnt & (CAP - 1)][tid] = (unsigned short)(jb + e + 0);
            cnt += (LO2(k0) <= tau) ? 1 : 0;
            sbuf[cnt & (CAP - 1)][tid] = (unsigned short)(jb + e + 1);
            cnt += (HI2(k0) <= tau) ? 1 : 0;
            sbuf[cnt & (CAP - 1)][tid] = (unsigned short)(jb + e + 2);
            cnt += (LO2(k1) <= tau) ? 1 : 0;
            sbuf[cnt & (CAP - 1)][tid] = (unsigned short)(jb + e + 3);
            cnt += (HI2(k1) <= tau) ? 1 : 0;
        }
    }

    // ---- exact top-16 over the ~22 survivors (ascending index => reference ties) ----
    float nd[KK]; int ni[KK];
#pragma unroll
    for (int s = 0; s < KK; s++) { nd[s] = 3.4e38f; ni[s] = 0; }
    float worst = 3.4e38f; int wslot = 0;
    if (cnt < CAP) {
        for (int ii = 0; ii < cnt; ii++) {
            int j = sbuf[ii][tid];
            float4 cc = __ldg(&P[j]);
            float key = fmaf(-2.f, fmaf(q.x, cc.x, fmaf(q.y, cc.y, q.z * cc.z)), cc.w);
            if (key < worst) {
#pragma unroll
                for (int s = 0; s < KK; s++) if (s == wslot) { nd[s] = key; ni[s] = j; }
                worst = nd[0]; wslot = 0;
#pragma unroll
                for (int s = 1; s < KK; s++) if (nd[s] > worst) { worst = nd[s]; wslot = s; }
            }
        }
    } else {
        // overflow fallback (P ~ 1e-12): exact full rescan
        for (int j = 0; j < NN; j++) {
            float4 cc = __ldg(&P[j]);
            float key = fmaf(-2.f, fmaf(q.x, cc.x, fmaf(q.y, cc.y, q.z * cc.z)), cc.w);
            if (key < worst) {
#pragma unroll
                for (int s = 0; s < KK; s++) if (s == wslot) { nd[s] = key; ni[s] = j; }
                worst = nd[0]; wslot = 0;
#pragma unroll
                for (int s = 1; s < KK; s++) if (nd[s] > worst) { worst = nd[s]; wslot = s; }
            }
        }
    }

    // ---- epilogue: alpha over the 16 kept neighbors ----
    float gx = d_gcn[b][qn][0], gy = d_gcn[b][qn][1], gz = d_gcn[b][qn][2];
    float amin = 3.4e38f, amax = -3.4e38f, asum = 0.f, asq = 0.f;
#pragma unroll
    for (int s = 0; s < KK; s++) {
        int j = ni[s];
        float4 cc = __ldg(&P[j]);
        float vx = cc.x - q.x, vy = cc.y - q.y, vz = cc.z - q.z;
        float inv = 1.f / fmaxf(sqrtf(fmaf(vx, vx, fmaf(vy, vy, vz * vz))), NORM_EPSF);
        float al = fmaf(vx, gx, fmaf(vy, gy, vz * gz)) * inv;
        amin = fminf(amin, al); amax = fmaxf(amax, al);
        asum += al; asq = fmaf(al, al, asq);
    }
    d_amin[b][qn] = amin; d_amax[b][qn] = amax;

    __shared__ float s1[TPB], s2[TPB];
    s1[tid] = asum; s2[tid] = asq;
    __syncthreads();
    for (int o = TPB / 2; o; o >>= 1) {
        if (tid < o) { s1[tid] += s1[tid + o]; s2[tid] += s2[tid + o]; }
        __syncthreads();
    }
    if (tid == 0) {
        atomicAdd(&d_sstat[2], (double)s1[0]);
        atomicAdd(&d_sstat[3], (double)s2[0]);
    }
}

// ---------------- K4: per-point 64-ch activation + 64->128 matvec ----------------
__global__ void __launch_bounds__(256) k_mlp(
    const float* __restrict__ W1d, const float* __restrict__ G1d, const float* __restrict__ B1d,
    const float* __restrict__ W2d,
    const float* __restrict__ W1a, const float* __restrict__ G1a, const float* __restrict__ B1a,
    const float* __restrict__ W2a) {
    __shared__ float sS[O1], sT[O1];
    __shared__ __align__(16) float sW[HH * O1];
    int tid = threadIdx.x;
    int i = blockIdx.x * 256 + tid;
    int b = i >> 13, n = i & (NN - 1);
    float gval = d_g[b][n];
    float amin = d_amin[b][n], amax = d_amax[b][n];

#pragma unroll
    for (int br = 0; br < 2; br++) {
        __syncthreads();
        double cnt = br ? (double)TOT * KK : (double)TOT;
        double mu = d_sstat[2 * br] / cnt;
        float vg = (float)(d_sstat[2 * br + 1] / cnt - mu * mu);
        float mg = (float)mu;
        const float* W1 = br ? W1a : W1d;
        const float* G1 = br ? G1a : G1d;
        const float* B1 = br ? B1a : B1d;
        const float* W2 = br ? W2a : W2d;
        if (tid < O1) {
            float w = W1[tid];
            float sc = w * G1[tid] * rsqrtf(fmaf(w * w, vg, BN_EPS));
            sS[tid] = sc;
            sT[tid] = fmaf(-mg, sc, B1[tid]);
        }
        for (int x = tid; x < HH * O1 / 4; x += 256)
            reinterpret_cast<float4*>(sW)[x] = reinterpret_cast<const float4*>(W2)[x];
        __syncthreads();

        float act[O1];
#pragma unroll
        for (int o = 0; o < O1; o++) {
            float s = sS[o];
            float x = br ? (s >= 0.f ? amax : amin) : gval;
            float y = fmaf(x, s, sT[o]);
            act[o] = y >= 0.f ? y : SLOPE * y;
        }

        float* pre = &d_pre[br][b][0][n];
        for (int h0 = 0; h0 < HH; h0 += 4) {
            float a0 = 0.f, a1 = 0.f, a2 = 0.f, a3 = 0.f;
#pragma unroll
            for (int o = 0; o < O1; o += 4) {
                float4 w0 = *reinterpret_cast<const float4*>(&sW[(h0 + 0) * O1 + o]);
                float4 w1 = *reinterpret_cast<const float4*>(&sW[(h0 + 1) * O1 + o]);
                float4 w2 = *reinterpret_cast<const float4*>(&sW[(h0 + 2) * O1 + o]);
                float4 w3 = *reinterpret_cast<const float4*>(&sW[(h0 + 3) * O1 + o]);
                a0 = fmaf(w0.x, act[o], fmaf(w0.y, act[o + 1], fmaf(w0.z, act[o + 2], fmaf(w0.w, act[o + 3], a0))));
                a1 = fmaf(w1.x, act[o], fmaf(w1.y, act[o + 1], fmaf(w1.z, act[o + 2], fmaf(w1.w, act[o + 3], a1))));
                a2 = fmaf(w2.x, act[o], fmaf(w2.y, act[o + 1], fmaf(w2.z, act[o + 2], fmaf(w2.w, act[o + 3], a2))));
                a3 = fmaf(w3.x, act[o], fmaf(w3.y, act[o + 1], fmaf(w3.z, act[o + 2], fmaf(w3.w, act[o + 3], a3))));
            }
            pre[(h0 + 0) * NN] = a0;
            pre[(h0 + 1) * NN] = a1;
            pre[(h0 + 2) * NN] = a2;
            pre[(h0 + 3) * NN] = a3;
        }
    }
}

// ---------------- K4b: per-channel BN stats for layer 2 ----------------
__global__ void k_cstat() {
    int br = blockIdx.x >> 7;
    int h = blockIdx.x & 127;
    float s = 0.f, q = 0.f;
    for (int bb = 0; bb < BB; bb++) {
        const float* row = &d_pre[br][bb][h][0];
        for (int n = threadIdx.x; n < NN; n += 256) {
            float v = row[n];
            s += v; q = fmaf(v, v, q);
        }
    }
    __shared__ float s1[256], s2[256];
    s1[threadIdx.x] = s; s2[threadIdx.x] = q;
    __syncthreads();
    for (int o = 128; o; o >>= 1) {
        if (threadIdx.x < o) { s1[threadIdx.x] += s1[threadIdx.x + o]; s2[threadIdx.x] += s2[threadIdx.x + o]; }
        __syncthreads();
    }
    if (threadIdx.x == 0) {
        d_cstat[2 * br][h] = (double)s1[0];
        d_cstat[2 * br + 1][h] = (double)s2[0];
    }
}

// ---------------- K5: final BN + LeakyReLU + concat write ----------------
__global__ void k_out(const float* __restrict__ G2d, const float* __restrict__ B2d,
                      const float* __restrict__ G2a, const float* __restrict__ B2a,
                      float* __restrict__ out) {
    __shared__ float sc[2 * HH], sh[2 * HH];
    int tid = threadIdx.x;
    if (tid < 2 * HH) {
        int br = tid >> 7, h = tid & 127;
        double mu = d_cstat[2 * br][h] / TOT;
        float var = (float)(d_cstat[2 * br + 1][h] / TOT - mu * mu);
        float gam = br ? G2a[h] : G2d[h];
        float bet = br ? B2a[h] : B2d[h];
        float s = gam * rsqrtf(var + BN_EPS);
        sc[tid] = s;
        sh[tid] = fmaf(-(float)mu, s, bet);
    }
    __syncthreads();
    const int total = BB * 2 * HH * NN;
    for (int idx = blockIdx.x * 256 + tid; idx < total; idx += gridDim.x * 256) {
        int b = idx >> 21;
        int c = (idx >> 13) & 255;
        int n = idx & (NN - 1);
        float v = d_pre[c >> 7][b][c & 127][n];
        float y = fmaf(v, sc[c], sh[c]);
        out[idx] = y >= 0.f ? y : SLOPE * y;
    }
}

// ---------------- launcher ----------------
extern "C" void kernel_launch(void* const* d_in, const int* in_sizes, int n_in,
                              void* d_out, int out_size) {
    const float* pts = (const float*)d_in[0];
    int base = 2;
    if (n_in >= 2 && in_sizes[1] > 1) base = 1;
    const float* W1d = (const float*)d_in[base + 0];
    const float* G1d = (const float*)d_in[base + 1];
    const float* B1d = (const float*)d_in[base + 2];
    const float* W2d = (const float*)d_in[base + 3];
    const float* G2d = (const float*)d_in[base + 4];
    const float* B2d = (const float*)d_in[base + 5];
    const float* W1a = (const float*)d_in[base + 6];
    const float* G1a = (const float*)d_in[base + 7];
    const float* B1a = (const float*)d_in[base + 8];
    const float* W2a = (const float*)d_in[base + 9];
    const float* G2a = (const float*)d_in[base + 10];
    const float* B2a = (const float*)d_in[base + 11];
    float* out = (float*)d_out;

    k_zero<<<1, 32>>>();
    k_centroid<<<12, 256>>>(pts);
    k_prep<<<TOT / 256, 256>>>(pts);
    k_knn<<<TOT / TPB, TPB>>>();
    k_mlp<<<TOT / 256, 256>>>(W1d, G1d, B1d, W2d, W1a, G1a, B1a, W2a);
    k_cstat<<<2 * HH, 256>>>();
    k_out<<<512, 256>>>(G2d, B2d, G2a, B2a, out);
}

// round 11
// speedup vs baseline: 1.8171x; 1.0357x over previous
#include <cuda_runtime.h>
#include <cstdint>

#define BB 4
#define NN 8192
#define KK 16
#define O1 64
#define HH 128
#define TOT (BB*NN)
#define BN_EPS 1e-5f
#define NORM_EPSF 1e-12f
#define SLOPE 0.2f

// knn config: one lane per query, 2-round fused threshold scan
#define TPB 128               // threads (=queries) per block
#define TILE 512              // candidates per smem tile
#define HALF (NN/2)           // 4096: round-A candidate count
#define NITH (HALF/TILE)      // 8 tile iterations per half
#define CAPH 64               // survivor capacity per query per half

typedef unsigned long long u64;
__device__ __forceinline__ u64 FMA2(u64 a, u64 b, u64 c) {
    u64 d; asm("fma.rn.f32x2 %0, %1, %2, %3;" : "=l"(d) : "l"(a), "l"(b), "l"(c)); return d;
}
__device__ __forceinline__ u64 MUL2(u64 a, u64 b) {
    u64 d; asm("mul.rn.f32x2 %0, %1, %2;" : "=l"(d) : "l"(a), "l"(b)); return d;
}
__device__ __forceinline__ float LO2(u64 v) { return __uint_as_float((unsigned)v); }
__device__ __forceinline__ float HI2(u64 v) { return __uint_as_float((unsigned)(v >> 32)); }
__device__ __forceinline__ u64 BC2(float v) { unsigned u = __float_as_uint(v); return (u64)u | ((u64)u << 32); }

// ---------------- scratch (static device globals; no allocation) ----------------
__device__ float  d_cent[BB][3];
__device__ float  d_g[BB][NN];
__device__ float  d_gcn[BB][NN][3];
__device__ float4 d_pts4[BB][NN];          // packed (x,y,z,|p|^2)
__device__ double d_sstat[4];
__device__ float  d_amin[BB][NN];
__device__ float  d_amax[BB][NN];
__device__ float  d_pre[2][BB][HH][NN];
__device__ double d_cstat[4][HH];

// ---------------- K0 ----------------
__global__ void k_zero() {
    if (threadIdx.x < 4) d_sstat[threadIdx.x] = 0.0;
}

// ---------------- K1: centroid ----------------
__global__ void k_centroid(const float* __restrict__ pts) {
    int b = blockIdx.x / 3, c = blockIdx.x % 3;
    const float* p = pts + (b * 3 + c) * NN;
    float s = 0.f;
    for (int n = threadIdx.x; n < NN; n += 256) s += p[n];
    __shared__ float sm[256];
    sm[threadIdx.x] = s; __syncthreads();
    for (int o = 128; o; o >>= 1) {
        if (threadIdx.x < o) sm[threadIdx.x] += sm[threadIdx.x + o];
        __syncthreads();
    }
    if (threadIdx.x == 0) d_cent[b][c] = sm[0] * (1.f / NN);
}

// ---------------- K2: g, normalized p2gc, g stats, packed pts4 ----------------
__global__ void k_prep(const float* __restrict__ pts) {
    int i = blockIdx.x * 256 + threadIdx.x;
    int b = i >> 13, n = i & (NN - 1);
    float x = pts[(b * 3 + 0) * NN + n];
    float y = pts[(b * 3 + 1) * NN + n];
    float z = pts[(b * 3 + 2) * NN + n];
    d_pts4[b][n] = make_float4(x, y, z, fmaf(x, x, fmaf(y, y, z * z)));

    float vx = x - d_cent[b][0];
    float vy = y - d_cent[b][1];
    float vz = z - d_cent[b][2];
    float g = vx * vx + vy * vy + vz * vz;
    d_g[b][n] = g;
    float inv = 1.f / fmaxf(sqrtf(g), NORM_EPSF);
    d_gcn[b][n][0] = vx * inv;
    d_gcn[b][n][1] = vy * inv;
    d_gcn[b][n][2] = vz * inv;

    __shared__ float s1[256], s2[256];
    s1[threadIdx.x] = g; s2[threadIdx.x] = g * g;
    __syncthreads();
    for (int o = 128; o; o >>= 1) {
        if (threadIdx.x < o) { s1[threadIdx.x] += s1[threadIdx.x + o]; s2[threadIdx.x] += s2[threadIdx.x + o]; }
        __syncthreads();
    }
    if (threadIdx.x == 0) {
        atomicAdd(&d_sstat[0], (double)s1[0]);
        atomicAdd(&d_sstat[1], (double)s2[0]);
    }
}

// ---------------- K3: kNN, 2-round fused threshold scan ----------------
// Round A (cands 0..4095): 32 interleaved chunk minima -> tau (valid global bound).
// Round B (4096..8191): fused conditional-store pass with tau.
// Re-pass A: conditional-store pass with tau. Survivors: A-half slots [0,64), B-half [64,128).
__global__ void __launch_bounds__(TPB, 4) k_knn() {
    __shared__ __align__(16) float sx[TILE], sy[TILE], sz[TILE], sw[TILE];
    __shared__ unsigned short sbuf[2 * CAPH][TPB];         // [slot][lane]: conflict-free
    int tid = threadIdx.x;
    int b = blockIdx.x >> 6;                               // 64 blocks per batch
    int qn = ((blockIdx.x & 63) << 7) | tid;               // 128 queries per block
    const float4* __restrict__ P = &d_pts4[b][0];
    float4 q = P[qn];
    u64 qx2 = BC2(q.x), qy2 = BC2(q.y), qz2 = BC2(q.z), n22 = BC2(-2.f);

    // ---- round A pass 1: 32 interleaved chunk minima (chunks of 128) over cands [0,4096) ----
    float m[32];
#pragma unroll
    for (int i = 0; i < 32; i++) m[i] = 3.4e38f;

    for (int it = 0; it < NITH; it++) {
        __syncthreads();
#pragma unroll
        for (int r = 0; r < TILE / TPB; r++) {
            int e = r * TPB + tid;
            float4 c = P[it * TILE + e];
            sx[e] = c.x; sy[e] = c.y; sz[e] = c.z; sw[e] = c.w;
        }
        __syncthreads();
#pragma unroll 16
        for (int e = 0; e < TILE; e += 4) {
            ulonglong2 X = *(const ulonglong2*)(sx + e);
            ulonglong2 Y = *(const ulonglong2*)(sy + e);
            ulonglong2 Z = *(const ulonglong2*)(sz + e);
            ulonglong2 W = *(const ulonglong2*)(sw + e);
            u64 k0 = FMA2(n22, FMA2(qx2, X.x, FMA2(qy2, Y.x, MUL2(qz2, Z.x))), W.x);
            u64 k1 = FMA2(n22, FMA2(qx2, X.y, FMA2(qy2, Y.y, MUL2(qz2, Z.y))), W.y);
            m[(e + 0) & 31] = fminf(m[(e + 0) & 31], LO2(k0));
            m[(e + 1) & 31] = fminf(m[(e + 1) & 31], HI2(k0));
            m[(e + 2) & 31] = fminf(m[(e + 2) & 31], LO2(k1));
            m[(e + 3) & 31] = fminf(m[(e + 3) & 31], HI2(k1));
        }
    }

    // tau = 16th smallest of the 32 chunk minima of round A.
    // Bound proof: >=16 round-A keys are <= tau, so tau >= round-A 16th-smallest >= global 16th-smallest.
#pragma unroll
    for (int kk = 2; kk <= 32; kk <<= 1) {
#pragma unroll
        for (int j = kk >> 1; j > 0; j >>= 1) {
#pragma unroll
            for (int i = 0; i < 32; i++) {
                int ixj = i ^ j;
                if (ixj > i) {
                    bool up = ((i & kk) == 0);
                    float lo = fminf(m[i], m[ixj]);
                    float hi = fmaxf(m[i], m[ixj]);
                    m[i] = up ? lo : hi;
                    m[ixj] = up ? hi : lo;
                }
            }
        }
    }
    float tau = m[15];

    // ---- round B: fused conditional-store over cands [4096,8192), slots [64,128) ----
    int cntB = 0;
    for (int it = NITH; it < 2 * NITH; it++) {
        __syncthreads();
#pragma unroll
        for (int r = 0; r < TILE / TPB; r++) {
            int e = r * TPB + tid;
            float4 c = P[it * TILE + e];
            sx[e] = c.x; sy[e] = c.y; sz[e] = c.z; sw[e] = c.w;
        }
        __syncthreads();
        int jb = it * TILE;
#pragma unroll 8
        for (int e = 0; e < TILE; e += 4) {
            ulonglong2 X = *(const ulonglong2*)(sx + e);
            ulonglong2 Y = *(const ulonglong2*)(sy + e);
            ulonglong2 Z = *(const ulonglong2*)(sz + e);
            ulonglong2 W = *(const ulonglong2*)(sw + e);
            u64 k0 = FMA2(n22, FMA2(qx2, X.x, FMA2(qy2, Y.x, MUL2(qz2, Z.x))), W.x);
            u64 k1 = FMA2(n22, FMA2(qx2, X.y, FMA2(qy2, Y.y, MUL2(qz2, Z.y))), W.y);
            sbuf[CAPH + (cntB & (CAPH - 1))][tid] = (unsigned short)(jb + e + 0);
            cntB += (LO2(k0) <= tau) ? 1 : 0;
            sbuf[CAPH + (cntB & (CAPH - 1))][tid] = (unsigned short)(jb + e + 1);
            cntB += (HI2(k0) <= tau) ? 1 : 0;
            sbuf[CAPH + (cntB & (CAPH - 1))][tid] = (unsigned short)(jb + e + 2);
            cntB += (LO2(k1) <= tau) ? 1 : 0;
            sbuf[CAPH + (cntB & (CAPH - 1))][tid] = (unsigned short)(jb + e + 3);
            cntB += (HI2(k1) <= tau) ? 1 : 0;
        }
    }

    // ---- re-pass A: conditional-store over cands [0,4096), slots [0,64) ----
    int cntA = 0;
    for (int it = 0; it < NITH; it++) {
        __syncthreads();
#pragma unroll
        for (int r = 0; r < TILE / TPB; r++) {
            int e = r * TPB + tid;
            float4 c = P[it * TILE + e];
            sx[e] = c.x; sy[e] = c.y; sz[e] = c.z; sw[e] = c.w;
        }
        __syncthreads();
        int jb = it * TILE;
#pragma unroll 8
        for (int e = 0; e < TILE; e += 4) {
            ulonglong2 X = *(const ulonglong2*)(sx + e);
            ulonglong2 Y = *(const ulonglong2*)(sy + e);
            ulonglong2 Z = *(const ulonglong2*)(sz + e);
            ulonglong2 W = *(const ulonglong2*)(sw + e);
            u64 k0 = FMA2(n22, FMA2(qx2, X.x, FMA2(qy2, Y.x, MUL2(qz2, Z.x))), W.x);
            u64 k1 = FMA2(n22, FMA2(qx2, X.y, FMA2(qy2, Y.y, MUL2(qz2, Z.y))), W.y);
            sbuf[cntA & (CAPH - 1)][tid] = (unsigned short)(jb + e + 0);
            cntA += (LO2(k0) <= tau) ? 1 : 0;
            sbuf[cntA & (CAPH - 1)][tid] = (unsigned short)(jb + e + 1);
            cntA += (HI2(k0) <= tau) ? 1 : 0;
            sbuf[cntA & (CAPH - 1)][tid] = (unsigned short)(jb + e + 2);
            cntA += (LO2(k1) <= tau) ? 1 : 0;
            sbuf[cntA & (CAPH - 1)][tid] = (unsigned short)(jb + e + 3);
            cntA += (HI2(k1) <= tau) ? 1 : 0;
        }
    }

    // ---- exact top-16 over survivors: A-half first, then B-half (ascending index) ----
    float nd[KK]; int ni[KK];
#pragma unroll
    for (int s = 0; s < KK; s++) { nd[s] = 3.4e38f; ni[s] = 0; }
    float worst = 3.4e38f; int wslot = 0;
    if (cntA < CAPH && cntB < CAPH) {
#pragma unroll
        for (int h = 0; h < 2; h++) {
            int c = h ? cntB : cntA;
            int off = h ? CAPH : 0;
            for (int ii = 0; ii < c; ii++) {
                int j = sbuf[off + ii][tid];
                float4 cc = __ldg(&P[j]);
                float key = fmaf(-2.f, fmaf(q.x, cc.x, fmaf(q.y, cc.y, q.z * cc.z)), cc.w);
                if (key < worst) {
#pragma unroll
                    for (int s = 0; s < KK; s++) if (s == wslot) { nd[s] = key; ni[s] = j; }
                    worst = nd[0]; wslot = 0;
#pragma unroll
                    for (int s = 1; s < KK; s++) if (nd[s] > worst) { worst = nd[s]; wslot = s; }
                }
            }
        }
    } else {
        // overflow fallback (negligible probability): exact full rescan
        for (int j = 0; j < NN; j++) {
            float4 cc = __ldg(&P[j]);
            float key = fmaf(-2.f, fmaf(q.x, cc.x, fmaf(q.y, cc.y, q.z * cc.z)), cc.w);
            if (key < worst) {
#pragma unroll
                for (int s = 0; s < KK; s++) if (s == wslot) { nd[s] = key; ni[s] = j; }
                worst = nd[0]; wslot = 0;
#pragma unroll
                for (int s = 1; s < KK; s++) if (nd[s] > worst) { worst = nd[s]; wslot = s; }
            }
        }
    }

    // ---- epilogue: alpha over the 16 kept neighbors ----
    float gx = d_gcn[b][qn][0], gy = d_gcn[b][qn][1], gz = d_gcn[b][qn][2];
    float amin = 3.4e38f, amax = -3.4e38f, asum = 0.f, asq = 0.f;
#pragma unroll
    for (int s = 0; s < KK; s++) {
        int j = ni[s];
        float4 cc = __ldg(&P[j]);
        float vx = cc.x - q.x, vy = cc.y - q.y, vz = cc.z - q.z;
        float inv = 1.f / fmaxf(sqrtf(fmaf(vx, vx, fmaf(vy, vy, vz * vz))), NORM_EPSF);
        float al = fmaf(vx, gx, fmaf(vy, gy, vz * gz)) * inv;
        amin = fminf(amin, al); amax = fmaxf(amax, al);
        asum += al; asq = fmaf(al, al, asq);
    }
    d_amin[b][qn] = amin; d_amax[b][qn] = amax;

    __shared__ float s1[TPB], s2[TPB];
    s1[tid] = asum; s2[tid] = asq;
    __syncthreads();
    for (int o = TPB / 2; o; o >>= 1) {
        if (tid < o) { s1[tid] += s1[tid + o]; s2[tid] += s2[tid + o]; }
        __syncthreads();
    }
    if (tid == 0) {
        atomicAdd(&d_sstat[2], (double)s1[0]);
        atomicAdd(&d_sstat[3], (double)s2[0]);
    }
}

// ---------------- K4: per-point 64-ch activation + 64->128 matvec ----------------
__global__ void __launch_bounds__(256) k_mlp(
    const float* __restrict__ W1d, const float* __restrict__ G1d, const float* __restrict__ B1d,
    const float* __restrict__ W2d,
    const float* __restrict__ W1a, const float* __restrict__ G1a, const float* __restrict__ B1a,
    const float* __restrict__ W2a) {
    __shared__ float sS[O1], sT[O1];
    __shared__ __align__(16) float sW[HH * O1];
    int tid = threadIdx.x;
    int i = blockIdx.x * 256 + tid;
    int b = i >> 13, n = i & (NN - 1);
    float gval = d_g[b][n];
    float amin = d_amin[b][n], amax = d_amax[b][n];

#pragma unroll
    for (int br = 0; br < 2; br++) {
        __syncthreads();
        double cnt = br ? (double)TOT * KK : (double)TOT;
        double mu = d_sstat[2 * br] / cnt;
        float vg = (float)(d_sstat[2 * br + 1] / cnt - mu * mu);
        float mg = (float)mu;
        const float* W1 = br ? W1a : W1d;
        const float* G1 = br ? G1a : G1d;
        const float* B1 = br ? B1a : B1d;
        const float* W2 = br ? W2a : W2d;
        if (tid < O1) {
            float w = W1[tid];
            float sc = w * G1[tid] * rsqrtf(fmaf(w * w, vg, BN_EPS));
            sS[tid] = sc;
            sT[tid] = fmaf(-mg, sc, B1[tid]);
        }
        for (int x = tid; x < HH * O1 / 4; x += 256)
            reinterpret_cast<float4*>(sW)[x] = reinterpret_cast<const float4*>(W2)[x];
        __syncthreads();

        float act[O1];
#pragma unroll
        for (int o = 0; o < O1; o++) {
            float s = sS[o];
            float x = br ? (s >= 0.f ? amax : amin) : gval;
            float y = fmaf(x, s, sT[o]);
            act[o] = y >= 0.f ? y : SLOPE * y;
        }

        float* pre = &d_pre[br][b][0][n];
        for (int h0 = 0; h0 < HH; h0 += 4) {
            float a0 = 0.f, a1 = 0.f, a2 = 0.f, a3 = 0.f;
#pragma unroll
            for (int o = 0; o < O1; o += 4) {
                float4 w0 = *reinterpret_cast<const float4*>(&sW[(h0 + 0) * O1 + o]);
                float4 w1 = *reinterpret_cast<const float4*>(&sW[(h0 + 1) * O1 + o]);
                float4 w2 = *reinterpret_cast<const float4*>(&sW[(h0 + 2) * O1 + o]);
                float4 w3 = *reinterpret_cast<const float4*>(&sW[(h0 + 3) * O1 + o]);
                a0 = fmaf(w0.x, act[o], fmaf(w0.y, act[o + 1], fmaf(w0.z, act[o + 2], fmaf(w0.w, act[o + 3], a0))));
                a1 = fmaf(w1.x, act[o], fmaf(w1.y, act[o + 1], fmaf(w1.z, act[o + 2], fmaf(w1.w, act[o + 3], a1))));
                a2 = fmaf(w2.x, act[o], fmaf(w2.y, act[o + 1], fmaf(w2.z, act[o + 2], fmaf(w2.w, act[o + 3], a2))));
                a3 = fmaf(w3.x, act[o], fmaf(w3.y, act[o + 1], fmaf(w3.z, act[o + 2], fmaf(w3.w, act[o + 3], a3))));
            }
            pre[(h0 + 0) * NN] = a0;
            pre[(h0 + 1) * NN] = a1;
            pre[(h0 + 2) * NN] = a2;
            pre[(h0 + 3) * NN] = a3;
        }
    }
}

// ---------------- K4b: per-channel BN stats for layer 2 ----------------
__global__ void k_cstat() {
    int br = blockIdx.x >> 7;
    int h = blockIdx.x & 127;
    float s = 0.f, q = 0.f;
    for (int bb = 0; bb < BB; bb++) {
        const float* row = &d_pre[br][bb][h][0];
        for (int n = threadIdx.x; n < NN; n += 256) {
            float v = row[n];
            s += v; q = fmaf(v, v, q);
        }
    }
    __shared__ float s1[256], s2[256];
    s1[threadIdx.x] = s; s2[threadIdx.x] = q;
    __syncthreads();
    for (int o = 128; o; o >>= 1) {
        if (threadIdx.x < o) { s1[threadIdx.x] += s1[threadIdx.x + o]; s2[threadIdx.x] += s2[threadIdx.x + o]; }
        __syncthreads();
    }
    if (threadIdx.x == 0) {
        d_cstat[2 * br][h] = (double)s1[0];
        d_cstat[2 * br + 1][h] = (double)s2[0];
    }
}

// ---------------- K5: final BN + LeakyReLU + concat write ----------------
__global__ void k_out(const float* __restrict__ G2d, const float* __restrict__ B2d,
                      const float* __restrict__ G2a, const float* __restrict__ B2a,
                      float* __restrict__ out) {
    __shared__ float sc[2 * HH], sh[2 * HH];
    int tid = threadIdx.x;
    if (tid < 2 * HH) {
        int br = tid >> 7, h = tid & 127;
        double mu = d_cstat[2 * br][h] / TOT;
        float var = (float)(d_cstat[2 * br + 1][h] / TOT - mu * mu);
        float gam = br ? G2a[h] : G2d[h];
        float bet = br ? B2a[h] : B2d[h];
        float s = gam * rsqrtf(var + BN_EPS);
        sc[tid] = s;
        sh[tid] = fmaf(-(float)mu, s, bet);
    }
    __syncthreads();
    const int total = BB * 2 * HH * NN;
    for (int idx = blockIdx.x * 256 + tid; idx < total; idx += gridDim.x * 256) {
        int b = idx >> 21;
        int c = (idx >> 13) & 255;
        int n = idx & (NN - 1);
        float v = d_pre[c >> 7][b][c & 127][n];
        float y = fmaf(v, sc[c], sh[c]);
        out[idx] = y >= 0.f ? y : SLOPE * y;
    }
}

// ---------------- launcher ----------------
extern "C" void kernel_launch(void* const* d_in, const int* in_sizes, int n_in,
                              void* d_out, int out_size) {
    const float* pts = (const float*)d_in[0];
    int base = 2;
    if (n_in >= 2 && in_sizes[1] > 1) base = 1;
    const float* W1d = (const float*)d_in[base + 0];
    const float* G1d = (const float*)d_in[base + 1];
    const float* B1d = (const float*)d_in[base + 2];
    const float* W2d = (const float*)d_in[base + 3];
    const float* G2d = (const float*)d_in[base + 4];
    const float* B2d = (const float*)d_in[base + 5];
    const float* W1a = (const float*)d_in[base + 6];
    const float* G1a = (const float*)d_in[base + 7];
    const float* B1a = (const float*)d_in[base + 8];
    const float* W2a = (const float*)d_in[base + 9];
    const float* G2a = (const float*)d_in[base + 10];
    const float* B2a = (const float*)d_in[base + 11];
    float* out = (float*)d_out;

    k_zero<<<1, 32>>>();
    k_centroid<<<12, 256>>>(pts);
    k_prep<<<TOT / 256, 256>>>(pts);
    k_knn<<<TOT / TPB, TPB>>>();
    k_mlp<<<TOT / 256, 256>>>(W1d, G1d, B1d, W2d, W1a, G1a, B1a, W2a);
    k_cstat<<<2 * HH, 256>>>();
    k_out<<<512, 256>>>(G2d, B2d, G2a, B2a, out);
}